// round 5
// baseline (speedup 1.0000x reference)
#include <cuda_runtime.h>
#include <math.h>

// Problem constants
#define BATCH   4
#define CHANS   64
#define NBC     256                 // BATCH * CHANS
#define SPATIAL 524288              // 32*128*128 elements per (b,c)
#define SPAT4   131072              // SPATIAL / 4 (float4)
#define PARTS   8                   // reduction blocks per (b,c)
#define REDR    4                   // C // R = 64/16

// Deterministic scratch (no device allocation allowed)
__device__ float g_part_s [NBC * PARTS];
__device__ float g_part_ss[NBC * PARTS];
__device__ float g_gate   [NBC];

// ---------------------------------------------------------------------------
// Kernel 1: per-(b,c) partial sum / sum-of-squares.
// grid = (PARTS, NBC) = 2048 blocks, block = 256. Each block reads 16384
// float4 (256 KiB), 64 float4 per thread, fully coalesced. High unroll for
// front-batched LDG.128 (MLP >> 4 hides DRAM latency). Deterministic tree.
// ---------------------------------------------------------------------------
__global__ __launch_bounds__(256) void cca_reduce_kernel(const float4* __restrict__ x) {
    const int part = blockIdx.x;      // 0..PARTS-1
    const int bc   = blockIdx.y;      // 0..NBC-1
    const int tid  = threadIdx.x;

    const float4* p = x + (size_t)bc * SPAT4 + (size_t)part * (SPAT4 / PARTS);

    float s = 0.f, ss = 0.f;
    #pragma unroll 16
    for (int k = 0; k < 64; ++k) {
        float4 v = p[tid + k * 256];
        s  += v.x + v.y + v.z + v.w;
        ss += v.x * v.x + v.y * v.y + v.z * v.z + v.w * v.w;
    }

    // warp reduce
    #pragma unroll
    for (int o = 16; o > 0; o >>= 1) {
        s  += __shfl_xor_sync(0xffffffffu, s,  o);
        ss += __shfl_xor_sync(0xffffffffu, ss, o);
    }

    __shared__ float sh_s[8], sh_ss[8];
    const int w = tid >> 5;
    if ((tid & 31) == 0) { sh_s[w] = s; sh_ss[w] = ss; }
    __syncthreads();

    if (tid == 0) {
        float ts = 0.f, tss = 0.f;
        #pragma unroll
        for (int i = 0; i < 8; ++i) { ts += sh_s[i]; tss += sh_ss[i]; }
        g_part_s [bc * PARTS + part] = ts;
        g_part_ss[bc * PARTS + part] = tss;
    }
}

// ---------------------------------------------------------------------------
// Kernel 2: finish reduction + SE MLP. One block of 256 threads (thread = bc).
// y = std + mean; h = relu(w1 @ y + b1); g = sigmoid(w2 @ h + b2)
// ---------------------------------------------------------------------------
__global__ __launch_bounds__(256) void cca_se_kernel(const float* __restrict__ w1,
                                                     const float* __restrict__ b1,
                                                     const float* __restrict__ w2,
                                                     const float* __restrict__ b2) {
    const int t = threadIdx.x;        // bc index: b = t / CHANS, c = t % CHANS

    float s = 0.f, ss = 0.f;
    #pragma unroll
    for (int i = 0; i < PARTS; ++i) {
        s  += g_part_s [t * PARTS + i];
        ss += g_part_ss[t * PARTS + i];
    }
    const float invN = 1.0f / (float)SPATIAL;
    const float mean = s * invN;
    const float var  = fmaxf(ss * invN - mean * mean, 0.f);
    const float stdv = sqrtf(var);

    __shared__ float y[NBC];
    y[t] = stdv + mean;
    __syncthreads();

    __shared__ float h[BATCH * REDR];
    if (t < BATCH * REDR) {
        const int b = t / REDR;
        const int r = t % REDR;
        float acc = b1[r];
        #pragma unroll
        for (int c = 0; c < CHANS; ++c)
            acc += w1[r * CHANS + c] * y[b * CHANS + c];
        h[t] = fmaxf(acc, 0.f);
    }
    __syncthreads();

    const int b = t / CHANS;
    const int c = t % CHANS;
    float acc = b2[c];
    #pragma unroll
    for (int r = 0; r < REDR; ++r)
        acc += w2[c * REDR + r] * h[b * REDR + r];
    g_gate[t] = 1.0f / (1.0f + expf(-acc));
}

// ---------------------------------------------------------------------------
// Kernel 3: out = x * g[bc]. grid = (128, NBC) = 32768 blocks, block = 256,
// 4 float4 per thread, coalesced. Reads + writes 1 GiB.
// ---------------------------------------------------------------------------
__global__ __launch_bounds__(256) void cca_scale_kernel(const float4* __restrict__ x,
                                                        float4* __restrict__ out) {
    const int bc = blockIdx.y;
    const float g = __ldg(&g_gate[bc]);
    const size_t base = (size_t)bc * SPAT4;
    const int idx = blockIdx.x * 256 + threadIdx.x;   // 0..32767

    #pragma unroll
    for (int k = 0; k < 4; ++k) {
        const size_t i = base + idx + (size_t)k * (128 * 256);
        float4 v = x[i];
        v.x *= g; v.y *= g; v.z *= g; v.w *= g;
        out[i] = v;
    }
}

// ---------------------------------------------------------------------------
extern "C" void kernel_launch(void* const* d_in, const int* in_sizes, int n_in,
                              void* d_out, int out_size) {
    const float* x  = (const float*)d_in[0];   // [4,64,32,128,128]
    const float* w1 = (const float*)d_in[1];   // [4,64]
    const float* b1 = (const float*)d_in[2];   // [4]
    const float* w2 = (const float*)d_in[3];   // [64,4]
    const float* b2 = (const float*)d_in[4];   // [64]
    float* out = (float*)d_out;

    cca_reduce_kernel<<<dim3(PARTS, NBC), 256>>>((const float4*)x);
    cca_se_kernel<<<1, 256>>>(w1, b1, w2, b2);
    cca_scale_kernel<<<dim3(128, NBC), 256>>>((const float4*)x, (float4*)out);
}